// round 15
// baseline (speedup 1.0000x reference)
#include <cuda_runtime.h>
#include <cstdint>

// ---------------------------------------------------------------------------
// GCN: out = segment_sum(feature[src], dst) @ W^T + b
// R15 = R14 resubmission (R14 died to container-infra flake before running).
// W hi/lo (tf32 split) precomputed ONCE into global uint2 pairs; GEMM CTAs
// N-split (64x64 output, grid x2) so the paired W half-tile fits in 51KB
// smem (4 CTAs/SM kept) and the B fragment path becomes a single
// LDS.64 -> MMA (no cvt/sub chain; R13 showed alu=26.5% from re-splitting
// the same W in all 782 CTAs). Sort chain + shfl-MLP reduce unchanged.
// ---------------------------------------------------------------------------

#define MAX_NODES 50000
#define MAX_EDGES 625000
#define DIM 128
#define KH 64                     // k-half width
#define TILE_ROWS 64
#define TILE_NCOLS 64
#define SCAN_BLK 256
#define NUM_SCAN_BLOCKS ((MAX_NODES + SCAN_BLK - 1) / SCAN_BLK)  // 196

#define PAD_STRIDE 68             // 64 + 4 pad
#define SMEM_A_WORDS (TILE_ROWS * PAD_STRIDE)       // 4352 floats
#define SMEM_WP_U2   (TILE_NCOLS * PAD_STRIDE)      // 4352 uint2 = 8704 words
#define GEMM_SMEM_BYTES ((SMEM_A_WORDS + 2 * SMEM_WP_U2) * 4)  // 52224

__device__ float g_feat2[(size_t)MAX_NODES * DIM];  // 25.6 MB transformed feats
__device__ uint2 g_Wp[DIM * DIM];                   // W as (tf32_hi, lo) pairs
__device__ int   g_src[MAX_EDGES];
__device__ int   g_dst[MAX_EDGES];
__device__ int   g_esrc[MAX_EDGES];                 // src ids sorted by dst
__device__ int   g_count[MAX_NODES];
__device__ int   g_off[MAX_NODES + 1];
__device__ int   g_cursor[MAX_NODES];
__device__ int   g_bsum[NUM_SCAN_BLOCKS];
__device__ int   g_boff[NUM_SCAN_BLOCKS];
__device__ int   g_idx_is_64;

// tf32 round (RNA) of an f32, result as raw b32 bits
__device__ __forceinline__ unsigned tf32_hi(float x)
{
    unsigned u;
    asm("cvt.rna.tf32.f32 %0, %1;" : "=r"(u) : "f"(x));
    return u;
}

// D += A*B, m16n8k8 tf32 (row.col), fp32 accumulate
#define MMA_TF32(d, a0, a1, a2, a3, b0, b1)                                  \
    asm("mma.sync.aligned.m16n8k8.row.col.f32.tf32.tf32.f32 "                \
        "{%0,%1,%2,%3}, {%4,%5,%6,%7}, {%8,%9}, {%0,%1,%2,%3};"              \
        : "+f"(d[0]), "+f"(d[1]), "+f"(d[2]), "+f"(d[3])                     \
        : "r"(a0), "r"(a1), "r"(a2), "r"(a3), "r"(b0), "r"(b1))

// ---------------------------------------------------------------------------
// Prep: zero counts + width detect + W hi/lo pair precompute.
// ---------------------------------------------------------------------------
__global__ __launch_bounds__(256) void prep_kernel(
    const int* __restrict__ a, const int* __restrict__ b,
    const float* __restrict__ W)
{
    int i = blockIdx.x * blockDim.x + threadIdx.x;
    if (i < MAX_NODES) g_count[i] = 0;
    if (i < DIM * DIM) {
        float v = W[i];
        unsigned hi = tf32_hi(v);
        float lo = v - __uint_as_float(hi);
        g_Wp[i] = make_uint2(hi, __float_as_uint(lo));
    }
    if (blockIdx.x == 0 && threadIdx.x < 32) {
        int lane = threadIdx.x;
        int nonzero = 0;
        for (int j = 2 * lane + 1; j < 2048; j += 64)
            if (a[j] != 0 || b[j] != 0) nonzero = 1;
        unsigned any = __any_sync(0xFFFFFFFFu, nonzero);
        if (lane == 0) g_idx_is_64 = any ? 0 : 1;
    }
}

// ---------------------------------------------------------------------------
// Normalize indices to int scratch + histogram of dst.
// ---------------------------------------------------------------------------
__global__ __launch_bounds__(256) void normalize_hist_kernel(
    const int* __restrict__ src_words, const int* __restrict__ dst_words, int E)
{
    int i = blockIdx.x * blockDim.x + threadIdx.x;
    if (i >= E) return;
    int is64 = g_idx_is_64;
    int s = is64 ? src_words[2 * i] : src_words[i];
    int d = is64 ? dst_words[2 * i] : dst_words[i];
    g_src[i] = s;
    g_dst[i] = d;
    if ((unsigned)d < MAX_NODES && (unsigned)s < MAX_NODES)
        atomicAdd(&g_count[d], 1);
}

// ---------------------------------------------------------------------------
// Scan stages 1-3 (multi-CTA; validated ~5us).
// ---------------------------------------------------------------------------
__global__ __launch_bounds__(SCAN_BLK) void scan1_kernel()
{
    __shared__ int sp[SCAN_BLK];
    int t = threadIdx.x;
    int i = blockIdx.x * SCAN_BLK + t;
    int v = (i < MAX_NODES) ? g_count[i] : 0;
    sp[t] = v;
    __syncthreads();
    #pragma unroll
    for (int d = 1; d < SCAN_BLK; d <<= 1) {
        int u = (t >= d) ? sp[t - d] : 0;
        __syncthreads();
        sp[t] += u;
        __syncthreads();
    }
    if (i < MAX_NODES) g_off[i] = sp[t] - v;
    if (t == SCAN_BLK - 1) g_bsum[blockIdx.x] = sp[t];
}

__global__ __launch_bounds__(SCAN_BLK) void scan2_kernel()
{
    __shared__ int sp[SCAN_BLK];
    int t = threadIdx.x;
    int v = (t < NUM_SCAN_BLOCKS) ? g_bsum[t] : 0;
    sp[t] = v;
    __syncthreads();
    #pragma unroll
    for (int d = 1; d < SCAN_BLK; d <<= 1) {
        int u = (t >= d) ? sp[t - d] : 0;
        __syncthreads();
        sp[t] += u;
        __syncthreads();
    }
    if (t < NUM_SCAN_BLOCKS) g_boff[t] = sp[t] - v;
    if (t == SCAN_BLK - 1) g_off[MAX_NODES] = sp[t];
}

__global__ __launch_bounds__(256) void scan3_kernel()
{
    int i = blockIdx.x * blockDim.x + threadIdx.x;
    if (i >= MAX_NODES) return;
    int v = g_off[i] + g_boff[i >> 8];
    g_off[i] = v;
    g_cursor[i] = v;
}

// ---------------------------------------------------------------------------
// Bucket fill.
// ---------------------------------------------------------------------------
__global__ __launch_bounds__(256) void fill_kernel(int E)
{
    int i = blockIdx.x * blockDim.x + threadIdx.x;
    if (i >= E) return;
    int s = g_src[i];
    int d = g_dst[i];
    if ((unsigned)d >= MAX_NODES || (unsigned)s >= MAX_NODES) return;
    int pos = atomicAdd(&g_cursor[d], 1);
    g_esrc[pos] = s;
}

// ---------------------------------------------------------------------------
// Tensor-core GEMM, k-split + N-split:
//   feat2[m][n] = sum_k feature[m][k] * W[n][k]
// CTA: 64 rows x 64 cols. grid.x = 2 * row_blocks; bx&1 selects N-half.
// 8 warps: warp&3 -> 16-row block, warp>>2 -> 32-col half (4 n-tiles of 8).
// B fragments come pre-split from g_Wp via single LDS.64 (no cvt in loop).
// smem 51KB -> 4 CTAs/SM.
// ---------------------------------------------------------------------------
__global__ __launch_bounds__(256) void gemm_tc_kernel(
    const float* __restrict__ feature, int N)
{
    extern __shared__ float smem[];
    float* sA  = smem;                                          // [64][68]
    uint2* sWp = reinterpret_cast<uint2*>(smem + SMEM_A_WORDS); // [64][68] pairs

    int tid = threadIdx.x;
    int warp = tid >> 5, lane = tid & 31;
    int bx = blockIdx.x;
    int row0 = (bx >> 1) * TILE_ROWS;
    int ncta = (bx & 1) * TILE_NCOLS;   // CTA's N base (0 or 64)

    int mrow = (warp & 3) * 16;         // warp's 16-row block
    int ncol0 = (warp >> 2) * 32;       // warp's 32-col half within CTA tile
    int g = lane >> 2;                  // group id (0..7)
    int t = lane & 3;                   // thread-in-group (0..3)

    float acc[4][4];
    #pragma unroll
    for (int nt = 0; nt < 4; nt++)
        #pragma unroll
        for (int q = 0; q < 4; q++) acc[nt][q] = 0.f;

    #pragma unroll
    for (int h = 0; h < 2; h++) {
        if (h) __syncthreads();  // protect buffer reuse

        // Load W-pair k-half: 64 n-rows x 64 k (uint2, coalesced)
        for (int i = tid; i < TILE_NCOLS * KH; i += 256) {
            int n = i >> 6, kk = i & 63;
            sWp[n * PAD_STRIDE + kk] = g_Wp[(ncta + n) * DIM + h * KH + kk];
        }
        // Load A k-half (float4 coalesced; zero-pad row tail)
        for (int i = tid; i < TILE_ROWS * (KH / 4); i += 256) {
            int r = i >> 4, c4 = i & 15;
            int gr = row0 + r;
            float4 v = make_float4(0.f, 0.f, 0.f, 0.f);
            if (gr < N)
                v = reinterpret_cast<const float4*>(feature + (size_t)gr * DIM + h * KH)[c4];
            *reinterpret_cast<float4*>(sA + r * PAD_STRIDE + c4 * 4) = v;
        }
        __syncthreads();

        #pragma unroll 2
        for (int k0 = 0; k0 < KH; k0 += 8) {
            // A fragment: a0=(g,t) a1=(g+8,t) a2=(g,t+4) a3=(g+8,t+4)
            float a0 = sA[(mrow + g) * PAD_STRIDE + k0 + t];
            float a1 = sA[(mrow + g + 8) * PAD_STRIDE + k0 + t];
            float a2 = sA[(mrow + g) * PAD_STRIDE + k0 + t + 4];
            float a3 = sA[(mrow + g + 8) * PAD_STRIDE + k0 + t + 4];
            unsigned ah0 = tf32_hi(a0), ah1 = tf32_hi(a1);
            unsigned ah2 = tf32_hi(a2), ah3 = tf32_hi(a3);
            unsigned al0 = __float_as_uint(a0 - __uint_as_float(ah0));
            unsigned al1 = __float_as_uint(a1 - __uint_as_float(ah1));
            unsigned al2 = __float_as_uint(a2 - __uint_as_float(ah2));
            unsigned al3 = __float_as_uint(a3 - __uint_as_float(ah3));

            #pragma unroll
            for (int nt = 0; nt < 4; nt++) {
                int n0 = ncol0 + nt * 8;
                // Pre-split B fragments: one LDS.64 each
                uint2 b0p = sWp[(n0 + g) * PAD_STRIDE + k0 + t];
                uint2 b1p = sWp[(n0 + g) * PAD_STRIDE + k0 + t + 4];

                MMA_TF32(acc[nt], ah0, ah1, ah2, ah3, b0p.x, b1p.x);  // hi*hi
                MMA_TF32(acc[nt], ah0, ah1, ah2, ah3, b0p.y, b1p.y);  // hi*lo
                MMA_TF32(acc[nt], al0, al1, al2, al3, b0p.x, b1p.x);  // lo*hi
            }
        }
    }

    // Store: c0,c1 -> (row g, cols 2t,2t+1); c2,c3 -> (row g+8, same cols)
    int gr0 = row0 + mrow + g;
    int gr1 = gr0 + 8;
    #pragma unroll
    for (int nt = 0; nt < 4; nt++) {
        int col = ncta + ncol0 + nt * 8 + t * 2;
        if (gr0 < N) {
            float2 v = make_float2(acc[nt][0], acc[nt][1]);
            *reinterpret_cast<float2*>(g_feat2 + (size_t)gr0 * DIM + col) = v;
        }
        if (gr1 < N) {
            float2 v = make_float2(acc[nt][2], acc[nt][3]);
            *reinterpret_cast<float2*>(g_feat2 + (size_t)gr1 * DIM + col) = v;
        }
    }
}

// ---------------------------------------------------------------------------
// Reduce: one warp per node, coalesced index load + shfl broadcast, 8-deep
// gather MLP, single store with bias seed. No atomics. (validated ~30us)
// ---------------------------------------------------------------------------
__global__ __launch_bounds__(256) void reduce_kernel(
    const float* __restrict__ b, float* __restrict__ out, int N)
{
    int n = (blockIdx.x * blockDim.x + threadIdx.x) >> 5;
    int lane = threadIdx.x & 31;
    if (n >= N) return;

    int begin = g_off[n];
    int end   = g_off[n + 1];

    float4 acc = reinterpret_cast<const float4*>(b)[lane];  // bias seed

    for (int base = begin; base < end; base += 32) {
        int cnt = min(32, end - base);
        int idx = (lane < cnt) ? g_esrc[base + lane] : 0;

        int j = 0;
        for (; j + 8 <= cnt; j += 8) {
            int s0 = __shfl_sync(0xFFFFFFFFu, idx, j + 0);
            int s1 = __shfl_sync(0xFFFFFFFFu, idx, j + 1);
            int s2 = __shfl_sync(0xFFFFFFFFu, idx, j + 2);
            int s3 = __shfl_sync(0xFFFFFFFFu, idx, j + 3);
            int s4 = __shfl_sync(0xFFFFFFFFu, idx, j + 4);
            int s5 = __shfl_sync(0xFFFFFFFFu, idx, j + 5);
            int s6 = __shfl_sync(0xFFFFFFFFu, idx, j + 6);
            int s7 = __shfl_sync(0xFFFFFFFFu, idx, j + 7);
            float4 v0 = reinterpret_cast<const float4*>(g_feat2 + (size_t)s0 * DIM)[lane];
            float4 v1 = reinterpret_cast<const float4*>(g_feat2 + (size_t)s1 * DIM)[lane];
            float4 v2 = reinterpret_cast<const float4*>(g_feat2 + (size_t)s2 * DIM)[lane];
            float4 v3 = reinterpret_cast<const float4*>(g_feat2 + (size_t)s3 * DIM)[lane];
            float4 v4 = reinterpret_cast<const float4*>(g_feat2 + (size_t)s4 * DIM)[lane];
            float4 v5 = reinterpret_cast<const float4*>(g_feat2 + (size_t)s5 * DIM)[lane];
            float4 v6 = reinterpret_cast<const float4*>(g_feat2 + (size_t)s6 * DIM)[lane];
            float4 v7 = reinterpret_cast<const float4*>(g_feat2 + (size_t)s7 * DIM)[lane];
            acc.x += v0.x; acc.y += v0.y; acc.z += v0.z; acc.w += v0.w;
            acc.x += v1.x; acc.y += v1.y; acc.z += v1.z; acc.w += v1.w;
            acc.x += v2.x; acc.y += v2.y; acc.z += v2.z; acc.w += v2.w;
            acc.x += v3.x; acc.y += v3.y; acc.z += v3.z; acc.w += v3.w;
            acc.x += v4.x; acc.y += v4.y; acc.z += v4.z; acc.w += v4.w;
            acc.x += v5.x; acc.y += v5.y; acc.z += v5.z; acc.w += v5.w;
            acc.x += v6.x; acc.y += v6.y; acc.z += v6.z; acc.w += v6.w;
            acc.x += v7.x; acc.y += v7.y; acc.z += v7.z; acc.w += v7.w;
        }
        for (; j + 2 <= cnt; j += 2) {
            int s0 = __shfl_sync(0xFFFFFFFFu, idx, j + 0);
            int s1 = __shfl_sync(0xFFFFFFFFu, idx, j + 1);
            float4 v0 = reinterpret_cast<const float4*>(g_feat2 + (size_t)s0 * DIM)[lane];
            float4 v1 = reinterpret_cast<const float4*>(g_feat2 + (size_t)s1 * DIM)[lane];
            acc.x += v0.x; acc.y += v0.y; acc.z += v0.z; acc.w += v0.w;
            acc.x += v1.x; acc.y += v1.y; acc.z += v1.z; acc.w += v1.w;
        }
        for (; j < cnt; j++) {
            int s = __shfl_sync(0xFFFFFFFFu, idx, j);
            float4 v = reinterpret_cast<const float4*>(g_feat2 + (size_t)s * DIM)[lane];
            acc.x += v.x; acc.y += v.y; acc.z += v.z; acc.w += v.w;
        }
    }
    reinterpret_cast<float4*>(out + (size_t)n * DIM)[lane] = acc;
}

// ---------------------------------------------------------------------------
extern "C" void kernel_launch(void* const* d_in, const int* in_sizes, int n_in,
                              void* d_out, int out_size)
{
    // Identify inputs BY SIZE (robust to ordering and width reporting).
    const float* feature = nullptr;
    const float* W = nullptr;
    const float* b = nullptr;
    const int*   idx_words[2] = {nullptr, nullptr};
    int n_idx = 0;

    for (int i = 0; i < n_in; i++) {
        long long s = in_sizes[i];
        if (s == 128 || s == 512) {
            b = (const float*)d_in[i];
        } else if (s == 16384 || s == 65536) {
            W = (const float*)d_in[i];
        } else if (s == 625000 || s == 1250000 || s == 2500000 || s == 5000000) {
            if (n_idx < 2) idx_words[n_idx++] = (const int*)d_in[i];
        } else if (s == 6400000 || s == 25600000) {
            feature = (const float*)d_in[i];
        }
    }
    if (!feature || !W || !b || n_idx < 2) {  // positional fallback
        feature      = (const float*)d_in[0];
        idx_words[0] = (const int*)d_in[1];
        idx_words[1] = (const int*)d_in[2];
        W            = (const float*)d_in[3];
        b            = (const float*)d_in[4];
    }

    const int N = MAX_NODES;
    const int E = MAX_EDGES;
    float* out = (float*)d_out;

    cudaFuncSetAttribute(gemm_tc_kernel,
                         cudaFuncAttributeMaxDynamicSharedMemorySize,
                         GEMM_SMEM_BYTES);

    prep_kernel<<<(N + 255) / 256, 256>>>(idx_words[0], idx_words[1], W);
    normalize_hist_kernel<<<(E + 255) / 256, 256>>>(idx_words[0], idx_words[1], E);
    scan1_kernel<<<NUM_SCAN_BLOCKS, SCAN_BLK>>>();
    gemm_tc_kernel<<<2 * ((N + TILE_ROWS - 1) / TILE_ROWS), 256, GEMM_SMEM_BYTES>>>(feature, N);
    scan2_kernel<<<1, SCAN_BLK>>>();
    scan3_kernel<<<(N + 255) / 256, 256>>>();
    fill_kernel<<<(E + 255) / 256, 256>>>(E);
    reduce_kernel<<<(N * 32 + 255) / 256, 256>>>(b, out, N);
}

// round 16
// speedup vs baseline: 1.0870x; 1.0870x over previous
#include <cuda_runtime.h>
#include <cstdint>

// ---------------------------------------------------------------------------
// GCN: out = segment_sum(feature[src], dst) @ W^T + b
// R16: launch-topology change ONLY — fork/join streams so the independent
// sort chain (~22us) overlaps the 48us GEMM. Compute kernels identical to
// the 100.4us R15 baseline (W-split hoisted into its own tiny kernel on the
// side stream). Graph capture preserves the fork.
// ---------------------------------------------------------------------------

#define MAX_NODES 50000
#define MAX_EDGES 625000
#define DIM 128
#define KH 64                     // k-half width
#define TILE_ROWS 64
#define TILE_NCOLS 64
#define SCAN_BLK 256
#define NUM_SCAN_BLOCKS ((MAX_NODES + SCAN_BLK - 1) / SCAN_BLK)  // 196

#define PAD_STRIDE 68             // 64 + 4 pad
#define SMEM_A_WORDS (TILE_ROWS * PAD_STRIDE)       // 4352 floats
#define SMEM_WP_U2   (TILE_NCOLS * PAD_STRIDE)      // 4352 uint2 = 8704 words
#define GEMM_SMEM_BYTES ((SMEM_A_WORDS + 2 * SMEM_WP_U2) * 4)  // 52224

__device__ float g_feat2[(size_t)MAX_NODES * DIM];  // 25.6 MB transformed feats
__device__ uint2 g_Wp[DIM * DIM];                   // W as (tf32_hi, lo) pairs
__device__ int   g_src[MAX_EDGES];
__device__ int   g_dst[MAX_EDGES];
__device__ int   g_esrc[MAX_EDGES];                 // src ids sorted by dst
__device__ int   g_count[MAX_NODES];
__device__ int   g_off[MAX_NODES + 1];
__device__ int   g_cursor[MAX_NODES];
__device__ int   g_bsum[NUM_SCAN_BLOCKS];
__device__ int   g_boff[NUM_SCAN_BLOCKS];
__device__ int   g_idx_is_64;

// tf32 round (RNA) of an f32, result as raw b32 bits
__device__ __forceinline__ unsigned tf32_hi(float x)
{
    unsigned u;
    asm("cvt.rna.tf32.f32 %0, %1;" : "=r"(u) : "f"(x));
    return u;
}

// D += A*B, m16n8k8 tf32 (row.col), fp32 accumulate
#define MMA_TF32(d, a0, a1, a2, a3, b0, b1)                                  \
    asm("mma.sync.aligned.m16n8k8.row.col.f32.tf32.tf32.f32 "                \
        "{%0,%1,%2,%3}, {%4,%5,%6,%7}, {%8,%9}, {%0,%1,%2,%3};"              \
        : "+f"(d[0]), "+f"(d[1]), "+f"(d[2]), "+f"(d[3])                     \
        : "r"(a0), "r"(a1), "r"(a2), "r"(a3), "r"(b0), "r"(b1))

// ---------------------------------------------------------------------------
// W hi/lo pair precompute (side stream, feeds GEMM only).
// ---------------------------------------------------------------------------
__global__ __launch_bounds__(256) void wprep_kernel(const float* __restrict__ W)
{
    int i = blockIdx.x * blockDim.x + threadIdx.x;
    if (i < DIM * DIM) {
        float v = W[i];
        unsigned hi = tf32_hi(v);
        float lo = v - __uint_as_float(hi);
        g_Wp[i] = make_uint2(hi, __float_as_uint(lo));
    }
}

// ---------------------------------------------------------------------------
// Zero counts + index-width detect (main stream, feeds sort chain).
// ---------------------------------------------------------------------------
__global__ __launch_bounds__(256) void zero_detect_kernel(
    const int* __restrict__ a, const int* __restrict__ b)
{
    int i = blockIdx.x * blockDim.x + threadIdx.x;
    if (i < MAX_NODES) g_count[i] = 0;
    if (blockIdx.x == 0 && threadIdx.x < 32) {
        int lane = threadIdx.x;
        int nonzero = 0;
        for (int j = 2 * lane + 1; j < 2048; j += 64)
            if (a[j] != 0 || b[j] != 0) nonzero = 1;
        unsigned any = __any_sync(0xFFFFFFFFu, nonzero);
        if (lane == 0) g_idx_is_64 = any ? 0 : 1;
    }
}

// ---------------------------------------------------------------------------
// Normalize indices to int scratch + histogram of dst.
// ---------------------------------------------------------------------------
__global__ __launch_bounds__(256) void normalize_hist_kernel(
    const int* __restrict__ src_words, const int* __restrict__ dst_words, int E)
{
    int i = blockIdx.x * blockDim.x + threadIdx.x;
    if (i >= E) return;
    int is64 = g_idx_is_64;
    int s = is64 ? src_words[2 * i] : src_words[i];
    int d = is64 ? dst_words[2 * i] : dst_words[i];
    g_src[i] = s;
    g_dst[i] = d;
    if ((unsigned)d < MAX_NODES && (unsigned)s < MAX_NODES)
        atomicAdd(&g_count[d], 1);
}

// ---------------------------------------------------------------------------
// Scan stages 1-3 (multi-CTA; validated ~5us).
// ---------------------------------------------------------------------------
__global__ __launch_bounds__(SCAN_BLK) void scan1_kernel()
{
    __shared__ int sp[SCAN_BLK];
    int t = threadIdx.x;
    int i = blockIdx.x * SCAN_BLK + t;
    int v = (i < MAX_NODES) ? g_count[i] : 0;
    sp[t] = v;
    __syncthreads();
    #pragma unroll
    for (int d = 1; d < SCAN_BLK; d <<= 1) {
        int u = (t >= d) ? sp[t - d] : 0;
        __syncthreads();
        sp[t] += u;
        __syncthreads();
    }
    if (i < MAX_NODES) g_off[i] = sp[t] - v;
    if (t == SCAN_BLK - 1) g_bsum[blockIdx.x] = sp[t];
}

__global__ __launch_bounds__(SCAN_BLK) void scan2_kernel()
{
    __shared__ int sp[SCAN_BLK];
    int t = threadIdx.x;
    int v = (t < NUM_SCAN_BLOCKS) ? g_bsum[t] : 0;
    sp[t] = v;
    __syncthreads();
    #pragma unroll
    for (int d = 1; d < SCAN_BLK; d <<= 1) {
        int u = (t >= d) ? sp[t - d] : 0;
        __syncthreads();
        sp[t] += u;
        __syncthreads();
    }
    if (t < NUM_SCAN_BLOCKS) g_boff[t] = sp[t] - v;
    if (t == SCAN_BLK - 1) g_off[MAX_NODES] = sp[t];
}

__global__ __launch_bounds__(256) void scan3_kernel()
{
    int i = blockIdx.x * blockDim.x + threadIdx.x;
    if (i >= MAX_NODES) return;
    int v = g_off[i] + g_boff[i >> 8];
    g_off[i] = v;
    g_cursor[i] = v;
}

// ---------------------------------------------------------------------------
// Bucket fill.
// ---------------------------------------------------------------------------
__global__ __launch_bounds__(256) void fill_kernel(int E)
{
    int i = blockIdx.x * blockDim.x + threadIdx.x;
    if (i >= E) return;
    int s = g_src[i];
    int d = g_dst[i];
    if ((unsigned)d >= MAX_NODES || (unsigned)s >= MAX_NODES) return;
    int pos = atomicAdd(&g_cursor[d], 1);
    g_esrc[pos] = s;
}

// ---------------------------------------------------------------------------
// Tensor-core GEMM, k-split + N-split (identical to R15, 48us measured):
//   feat2[m][n] = sum_k feature[m][k] * W[n][k]
// ---------------------------------------------------------------------------
__global__ __launch_bounds__(256) void gemm_tc_kernel(
    const float* __restrict__ feature, int N)
{
    extern __shared__ float smem[];
    float* sA  = smem;                                          // [64][68]
    uint2* sWp = reinterpret_cast<uint2*>(smem + SMEM_A_WORDS); // [64][68] pairs

    int tid = threadIdx.x;
    int warp = tid >> 5, lane = tid & 31;
    int bx = blockIdx.x;
    int row0 = (bx >> 1) * TILE_ROWS;
    int ncta = (bx & 1) * TILE_NCOLS;   // CTA's N base (0 or 64)

    int mrow = (warp & 3) * 16;         // warp's 16-row block
    int ncol0 = (warp >> 2) * 32;       // warp's 32-col half within CTA tile
    int g = lane >> 2;                  // group id (0..7)
    int t = lane & 3;                   // thread-in-group (0..3)

    float acc[4][4];
    #pragma unroll
    for (int nt = 0; nt < 4; nt++)
        #pragma unroll
        for (int q = 0; q < 4; q++) acc[nt][q] = 0.f;

    #pragma unroll
    for (int h = 0; h < 2; h++) {
        if (h) __syncthreads();  // protect buffer reuse

        // Load W-pair k-half: 64 n-rows x 64 k (uint2, coalesced)
        for (int i = tid; i < TILE_NCOLS * KH; i += 256) {
            int n = i >> 6, kk = i & 63;
            sWp[n * PAD_STRIDE + kk] = g_Wp[(ncta + n) * DIM + h * KH + kk];
        }
        // Load A k-half (float4 coalesced; zero-pad row tail)
        for (int i = tid; i < TILE_ROWS * (KH / 4); i += 256) {
            int r = i >> 4, c4 = i & 15;
            int gr = row0 + r;
            float4 v = make_float4(0.f, 0.f, 0.f, 0.f);
            if (gr < N)
                v = reinterpret_cast<const float4*>(feature + (size_t)gr * DIM + h * KH)[c4];
            *reinterpret_cast<float4*>(sA + r * PAD_STRIDE + c4 * 4) = v;
        }
        __syncthreads();

        #pragma unroll 2
        for (int k0 = 0; k0 < KH; k0 += 8) {
            // A fragment: a0=(g,t) a1=(g+8,t) a2=(g,t+4) a3=(g+8,t+4)
            float a0 = sA[(mrow + g) * PAD_STRIDE + k0 + t];
            float a1 = sA[(mrow + g + 8) * PAD_STRIDE + k0 + t];
            float a2 = sA[(mrow + g) * PAD_STRIDE + k0 + t + 4];
            float a3 = sA[(mrow + g + 8) * PAD_STRIDE + k0 + t + 4];
            unsigned ah0 = tf32_hi(a0), ah1 = tf32_hi(a1);
            unsigned ah2 = tf32_hi(a2), ah3 = tf32_hi(a3);
            unsigned al0 = __float_as_uint(a0 - __uint_as_float(ah0));
            unsigned al1 = __float_as_uint(a1 - __uint_as_float(ah1));
            unsigned al2 = __float_as_uint(a2 - __uint_as_float(ah2));
            unsigned al3 = __float_as_uint(a3 - __uint_as_float(ah3));

            #pragma unroll
            for (int nt = 0; nt < 4; nt++) {
                int n0 = ncol0 + nt * 8;
                // Pre-split B fragments: one LDS.64 each
                uint2 b0p = sWp[(n0 + g) * PAD_STRIDE + k0 + t];
                uint2 b1p = sWp[(n0 + g) * PAD_STRIDE + k0 + t + 4];

                MMA_TF32(acc[nt], ah0, ah1, ah2, ah3, b0p.x, b1p.x);  // hi*hi
                MMA_TF32(acc[nt], ah0, ah1, ah2, ah3, b0p.y, b1p.y);  // hi*lo
                MMA_TF32(acc[nt], al0, al1, al2, al3, b0p.x, b1p.x);  // lo*hi
            }
        }
    }

    // Store: c0,c1 -> (row g, cols 2t,2t+1); c2,c3 -> (row g+8, same cols)
    int gr0 = row0 + mrow + g;
    int gr1 = gr0 + 8;
    #pragma unroll
    for (int nt = 0; nt < 4; nt++) {
        int col = ncta + ncol0 + nt * 8 + t * 2;
        if (gr0 < N) {
            float2 v = make_float2(acc[nt][0], acc[nt][1]);
            *reinterpret_cast<float2*>(g_feat2 + (size_t)gr0 * DIM + col) = v;
        }
        if (gr1 < N) {
            float2 v = make_float2(acc[nt][2], acc[nt][3]);
            *reinterpret_cast<float2*>(g_feat2 + (size_t)gr1 * DIM + col) = v;
        }
    }
}

// ---------------------------------------------------------------------------
// Reduce: one warp per node, coalesced index load + shfl broadcast, 8-deep
// gather MLP, single store with bias seed. No atomics. (~30us, at L2 floor)
// ---------------------------------------------------------------------------
__global__ __launch_bounds__(256) void reduce_kernel(
    const float* __restrict__ b, float* __restrict__ out, int N)
{
    int n = (blockIdx.x * blockDim.x + threadIdx.x) >> 5;
    int lane = threadIdx.x & 31;
    if (n >= N) return;

    int begin = g_off[n];
    int end   = g_off[n + 1];

    float4 acc = reinterpret_cast<const float4*>(b)[lane];  // bias seed

    for (int base = begin; base < end; base += 32) {
        int cnt = min(32, end - base);
        int idx = (lane < cnt) ? g_esrc[base + lane] : 0;

        int j = 0;
        for (; j + 8 <= cnt; j += 8) {
            int s0 = __shfl_sync(0xFFFFFFFFu, idx, j + 0);
            int s1 = __shfl_sync(0xFFFFFFFFu, idx, j + 1);
            int s2 = __shfl_sync(0xFFFFFFFFu, idx, j + 2);
            int s3 = __shfl_sync(0xFFFFFFFFu, idx, j + 3);
            int s4 = __shfl_sync(0xFFFFFFFFu, idx, j + 4);
            int s5 = __shfl_sync(0xFFFFFFFFu, idx, j + 5);
            int s6 = __shfl_sync(0xFFFFFFFFu, idx, j + 6);
            int s7 = __shfl_sync(0xFFFFFFFFu, idx, j + 7);
            float4 v0 = reinterpret_cast<const float4*>(g_feat2 + (size_t)s0 * DIM)[lane];
            float4 v1 = reinterpret_cast<const float4*>(g_feat2 + (size_t)s1 * DIM)[lane];
            float4 v2 = reinterpret_cast<const float4*>(g_feat2 + (size_t)s2 * DIM)[lane];
            float4 v3 = reinterpret_cast<const float4*>(g_feat2 + (size_t)s3 * DIM)[lane];
            float4 v4 = reinterpret_cast<const float4*>(g_feat2 + (size_t)s4 * DIM)[lane];
            float4 v5 = reinterpret_cast<const float4*>(g_feat2 + (size_t)s5 * DIM)[lane];
            float4 v6 = reinterpret_cast<const float4*>(g_feat2 + (size_t)s6 * DIM)[lane];
            float4 v7 = reinterpret_cast<const float4*>(g_feat2 + (size_t)s7 * DIM)[lane];
            acc.x += v0.x; acc.y += v0.y; acc.z += v0.z; acc.w += v0.w;
            acc.x += v1.x; acc.y += v1.y; acc.z += v1.z; acc.w += v1.w;
            acc.x += v2.x; acc.y += v2.y; acc.z += v2.z; acc.w += v2.w;
            acc.x += v3.x; acc.y += v3.y; acc.z += v3.z; acc.w += v3.w;
            acc.x += v4.x; acc.y += v4.y; acc.z += v4.z; acc.w += v4.w;
            acc.x += v5.x; acc.y += v5.y; acc.z += v5.z; acc.w += v5.w;
            acc.x += v6.x; acc.y += v6.y; acc.z += v6.z; acc.w += v6.w;
            acc.x += v7.x; acc.y += v7.y; acc.z += v7.z; acc.w += v7.w;
        }
        for (; j + 2 <= cnt; j += 2) {
            int s0 = __shfl_sync(0xFFFFFFFFu, idx, j + 0);
            int s1 = __shfl_sync(0xFFFFFFFFu, idx, j + 1);
            float4 v0 = reinterpret_cast<const float4*>(g_feat2 + (size_t)s0 * DIM)[lane];
            float4 v1 = reinterpret_cast<const float4*>(g_feat2 + (size_t)s1 * DIM)[lane];
            acc.x += v0.x; acc.y += v0.y; acc.z += v0.z; acc.w += v0.w;
            acc.x += v1.x; acc.y += v1.y; acc.z += v1.z; acc.w += v1.w;
        }
        for (; j < cnt; j++) {
            int s = __shfl_sync(0xFFFFFFFFu, idx, j);
            float4 v = reinterpret_cast<const float4*>(g_feat2 + (size_t)s * DIM)[lane];
            acc.x += v.x; acc.y += v.y; acc.z += v.z; acc.w += v.w;
        }
    }
    reinterpret_cast<float4*>(out + (size_t)n * DIM)[lane] = acc;
}

// ---------------------------------------------------------------------------
extern "C" void kernel_launch(void* const* d_in, const int* in_sizes, int n_in,
                              void* d_out, int out_size)
{
    // Identify inputs BY SIZE (robust to ordering and width reporting).
    const float* feature = nullptr;
    const float* W = nullptr;
    const float* b = nullptr;
    const int*   idx_words[2] = {nullptr, nullptr};
    int n_idx = 0;

    for (int i = 0; i < n_in; i++) {
        long long s = in_sizes[i];
        if (s == 128 || s == 512) {
            b = (const float*)d_in[i];
        } else if (s == 16384 || s == 65536) {
            W = (const float*)d_in[i];
        } else if (s == 625000 || s == 1250000 || s == 2500000 || s == 5000000) {
            if (n_idx < 2) idx_words[n_idx++] = (const int*)d_in[i];
        } else if (s == 6400000 || s == 25600000) {
            feature = (const float*)d_in[i];
        }
    }
    if (!feature || !W || !b || n_idx < 2) {  // positional fallback
        feature      = (const float*)d_in[0];
        idx_words[0] = (const int*)d_in[1];
        idx_words[1] = (const int*)d_in[2];
        W            = (const float*)d_in[3];
        b            = (const float*)d_in[4];
    }

    const int N = MAX_NODES;
    const int E = MAX_EDGES;
    float* out = (float*)d_out;

    cudaFuncSetAttribute(gemm_tc_kernel,
                         cudaFuncAttributeMaxDynamicSharedMemorySize,
                         GEMM_SMEM_BYTES);

    // Fork: side stream runs W-split + GEMM, main stream runs the sort chain.
    cudaStream_t s1;
    cudaStreamCreateWithFlags(&s1, cudaStreamNonBlocking);
    cudaEvent_t evFork, evGemm;
    cudaEventCreateWithFlags(&evFork, cudaEventDisableTiming);
    cudaEventCreateWithFlags(&evGemm, cudaEventDisableTiming);

    cudaEventRecord(evFork, 0);
    cudaStreamWaitEvent(s1, evFork, 0);
    wprep_kernel<<<(DIM * DIM + 255) / 256, 256, 0, s1>>>(W);
    gemm_tc_kernel<<<2 * ((N + TILE_ROWS - 1) / TILE_ROWS), 256,
                     GEMM_SMEM_BYTES, s1>>>(feature, N);
    cudaEventRecord(evGemm, s1);

    // Main (captured) stream: sort chain
    zero_detect_kernel<<<(N + 255) / 256, 256>>>(idx_words[0], idx_words[1]);
    normalize_hist_kernel<<<(E + 255) / 256, 256>>>(idx_words[0], idx_words[1], E);
    scan1_kernel<<<NUM_SCAN_BLOCKS, SCAN_BLK>>>();
    scan2_kernel<<<1, SCAN_BLK>>>();
    scan3_kernel<<<(N + 255) / 256, 256>>>();
    fill_kernel<<<(E + 255) / 256, 256>>>(E);

    // Join, then reduce (needs feat2 + sorted edge lists)
    cudaStreamWaitEvent(0, evGemm, 0);
    reduce_kernel<<<(N * 32 + 255) / 256, 256>>>(b, out, N);

    cudaEventDestroy(evFork);
    cudaEventDestroy(evGemm);
    cudaStreamDestroy(s1);
}